// round 10
// baseline (speedup 1.0000x reference)
#include <cuda_runtime.h>
#include <cuda_bf16.h>
#include <math.h>

// CropRoi: f (B=4, C=64, 32,32,32) f32; proposals (N,8) [b,score,cx,cy,cz,sx,sy,sz]
// out (N,C,7,7,7) f32. dims_max=32, R=7. L = c1-c0 in [2,13] => bin widths in [1,3].
//
// Strategy (R8 structure, CG=8): block = (proposal n, 8-channel group).
// All channels share bin bounds; each thread computes its bin's gather ONCE and
// accumulates 8 channels via fixed-immediate-offset LDGs (amortizes all loop
// and address arithmetic 8x, 8-wide MLP per iteration).

#define R_BINS 7
#define C_CH   64
#define DIMMAX 32
#define CG     8            // channels per thread
#define NTHREADS 352
#define CHSTRIDE 32768      // floats per (b,c) volume: 32^3

__global__ __launch_bounds__(NTHREADS) void crop_roi_kernel(
        const float* __restrict__ f,
        const float* __restrict__ props,
        float* __restrict__ out) {
    const int n  = blockIdx.x;
    const int cb = blockIdx.y * CG;
    const int tid = threadIdx.x;

    __shared__ int sS[3][R_BINS], sE[3][R_BINS];
    __shared__ int sB;

    // ---- bounds (21 threads), bitwise-identical to reference math ----
    if (tid < 3 * R_BINS) {
        const int ax = tid / R_BINS;
        const int bi = tid - ax * R_BINS;
        const float* p = props + (size_t)n * 8;
        if (tid == 0) sB = (int)p[0];
        float center = __ldg(p + 2 + ax);
        float side   = __ldg(p + 5 + ax);
        // *0.5f and *0.25f exact (powers of two) -> matches jnp arithmetic
        int c0 = (int)floorf((center - 0.5f * side) * 0.25f);
        int c1 = (int)ceilf ((center + 0.5f * side) * 0.25f);
        c0 = max(c0, 0);
        c1 = min(c1, DIMMAX);
        int L  = c1 - c0;
        int ss = c0 + (bi * L) / R_BINS;                     // floor div
        int ee = c0 + ((bi + 1) * L + R_BINS - 1) / R_BINS;  // ceil div
        ee = min(ee, ss + 6);                                // K cap (safety)
        sS[ax][bi] = ss;
        sE[ax][bi] = ee;
    }
    __syncthreads();

    if (tid >= 343) return;

    const int i   = tid / 49;
    const int rem = tid - i * 49;
    const int j   = rem / 7;
    const int k   = rem - j * 7;

    const int sd = sS[0][i], ed = sE[0][i];
    const int sh = sS[1][j], eh = sE[1][j];
    const int sw = sS[2][k], ew = sE[2][k];

    const float* base = f + (((size_t)sB * C_CH + cb) << 15);

    const float NEG = -3.402823466e+38f;   // finfo(float32).min
    float m0 = NEG, m1 = NEG, m2 = NEG, m3 = NEG;
    float m4 = NEG, m5 = NEG, m6 = NEG, m7 = NEG;

    for (int d = sd; d < ed; d++) {
        const float* pd = base + (d << 10);
        for (int h = sh; h < eh; h++) {
            const float* p = pd + (h << 5) + sw;
            for (int w = sw; w < ew; w++, p++) {
                // fixed byte offsets c*131072 -> encoded in LDG immediates
                float v0 = p[0 * CHSTRIDE];
                float v1 = p[1 * CHSTRIDE];
                float v2 = p[2 * CHSTRIDE];
                float v3 = p[3 * CHSTRIDE];
                float v4 = p[4 * CHSTRIDE];
                float v5 = p[5 * CHSTRIDE];
                float v6 = p[6 * CHSTRIDE];
                float v7 = p[7 * CHSTRIDE];
                m0 = fmaxf(m0, v0);
                m1 = fmaxf(m1, v1);
                m2 = fmaxf(m2, v2);
                m3 = fmaxf(m3, v3);
                m4 = fmaxf(m4, v4);
                m5 = fmaxf(m5, v5);
                m6 = fmaxf(m6, v6);
                m7 = fmaxf(m7, v7);
            }
        }
    }

    size_t o = ((size_t)n * C_CH + cb) * 343 + tid;
    out[o]           = m0;
    out[o + 1 * 343] = m1;
    out[o + 2 * 343] = m2;
    out[o + 3 * 343] = m3;
    out[o + 4 * 343] = m4;
    out[o + 5 * 343] = m5;
    out[o + 6 * 343] = m6;
    out[o + 7 * 343] = m7;
}

extern "C" void kernel_launch(void* const* d_in, const int* in_sizes, int n_in,
                              void* d_out, int out_size) {
    const float* f     = (const float*)d_in[0];
    const float* props = (const float*)d_in[2];
    float* out = (float*)d_out;

    int n_props = in_sizes[2] / 8;
    dim3 grid(n_props, C_CH / CG);
    crop_roi_kernel<<<grid, NTHREADS>>>(f, props, out);
}

// round 11
// speedup vs baseline: 1.1015x; 1.1015x over previous
#include <cuda_runtime.h>
#include <cuda_bf16.h>
#include <math.h>

// CropRoi: f (B=4, C=64, 32,32,32) f32; proposals (N,8) [b,score,cx,cy,cz,sx,sy,sz]
// out (N,C,7,7,7) f32. dims_max=32, R=7. L=c1-c0 in [2,13] => bin widths in [1,3].
//
// Structure: grid = (proposal n, chunk). Each proposal has 16 ch-groups x 343
// bins = 5488 outputs, split into 22 blocks of 256 threads (100% occ-capable,
// fine-grained balance). Bounds computed once per block in smem.
// Innermost w-window replaced by 3 clamp-duplicated unconditional loads
// (max is idempotent) -> no divergence, 12 batched LDGs per (d,h).

#define R_BINS 7
#define C_CH   64
#define DIMMAX 32
#define CG     4
#define NTHREADS 256
#define CHSTRIDE 32768              // floats per (b,c) volume: 32^3
#define PER_PROP (16 * 343)         // 5488 outputs (thread-level) per proposal
#define CHUNKS   ((PER_PROP + NTHREADS - 1) / NTHREADS)   // 22

__global__ __launch_bounds__(NTHREADS) void crop_roi_kernel(
        const float* __restrict__ f,
        const float* __restrict__ props,
        float* __restrict__ out) {
    const int n   = blockIdx.x;
    const int tid = threadIdx.x;

    __shared__ int sS[3][R_BINS], sE[3][R_BINS];
    __shared__ int sB;

    // ---- bounds (21 threads), bitwise-identical to reference math ----
    if (tid < 3 * R_BINS) {
        const int ax = tid / R_BINS;
        const int bi = tid - ax * R_BINS;
        const float* p = props + (size_t)n * 8;
        if (tid == 0) sB = (int)p[0];
        float center = __ldg(p + 2 + ax);
        float side   = __ldg(p + 5 + ax);
        // *0.5f and *0.25f exact (powers of two) -> matches jnp arithmetic
        int c0 = (int)floorf((center - 0.5f * side) * 0.25f);
        int c1 = (int)ceilf ((center + 0.5f * side) * 0.25f);
        c0 = max(c0, 0);
        c1 = min(c1, DIMMAX);
        int L  = c1 - c0;
        int ss = c0 + (bi * L) / R_BINS;                     // floor div
        int ee = c0 + ((bi + 1) * L + R_BINS - 1) / R_BINS;  // ceil div
        ee = min(ee, ss + 6);                                // K cap (safety)
        sS[ax][bi] = ss;
        sE[ax][bi] = ee;
    }
    __syncthreads();

    const int local = blockIdx.y * NTHREADS + tid;
    if (local >= PER_PROP) return;

    const int cg  = local / 343;            // compile-time magic div
    const int bin = local - cg * 343;
    const int i   = bin / 49;
    const int rem = bin - i * 49;
    const int j   = rem / 7;
    const int k   = rem - j * 7;

    const int sd = sS[0][i], ed = sE[0][i];
    const int sh = sS[1][j], eh = sE[1][j];
    const int w0 = sS[2][k];
    const int wl = sE[2][k] - 1;
    const int w1 = min(w0 + 1, wl);
    const int w2 = min(w0 + 2, wl);

    const float* base = f + (((size_t)sB * C_CH + cg * CG) << 15);

    const float NEG = -3.402823466e+38f;    // finfo(float32).min
    float m0 = NEG, m1 = NEG, m2 = NEG, m3 = NEG;

    for (int d = sd; d < ed; d++) {
        const float* pd = base + (d << 10);
        for (int h = sh; h < eh; h++) {
            const float* p = pd + (h << 5);
            // 12 unconditional loads, fixed immediate channel offsets
            float a0 = p[w0 + 0 * CHSTRIDE];
            float b0 = p[w1 + 0 * CHSTRIDE];
            float c0v = p[w2 + 0 * CHSTRIDE];
            float a1 = p[w0 + 1 * CHSTRIDE];
            float b1 = p[w1 + 1 * CHSTRIDE];
            float c1v = p[w2 + 1 * CHSTRIDE];
            float a2 = p[w0 + 2 * CHSTRIDE];
            float b2 = p[w1 + 2 * CHSTRIDE];
            float c2v = p[w2 + 2 * CHSTRIDE];
            float a3 = p[w0 + 3 * CHSTRIDE];
            float b3 = p[w1 + 3 * CHSTRIDE];
            float c3v = p[w2 + 3 * CHSTRIDE];
            m0 = fmaxf(m0, fmaxf(a0, fmaxf(b0, c0v)));
            m1 = fmaxf(m1, fmaxf(a1, fmaxf(b1, c1v)));
            m2 = fmaxf(m2, fmaxf(a2, fmaxf(b2, c2v)));
            m3 = fmaxf(m3, fmaxf(a3, fmaxf(b3, c3v)));
        }
    }

    size_t o = ((size_t)n * C_CH + cg * CG) * 343 + bin;
    out[o]           = m0;
    out[o + 1 * 343] = m1;
    out[o + 2 * 343] = m2;
    out[o + 3 * 343] = m3;
}

extern "C" void kernel_launch(void* const* d_in, const int* in_sizes, int n_in,
                              void* d_out, int out_size) {
    const float* f     = (const float*)d_in[0];
    const float* props = (const float*)d_in[2];
    float* out = (float*)d_out;

    int n_props = in_sizes[2] / 8;
    dim3 grid(n_props, CHUNKS);
    crop_roi_kernel<<<grid, NTHREADS>>>(f, props, out);
}

// round 12
// speedup vs baseline: 1.3200x; 1.1983x over previous
#include <cuda_runtime.h>
#include <cuda_bf16.h>
#include <math.h>

// CropRoi: f (B=4, C=64, 32,32,32) f32; proposals (N,8) [b,score,cx,cy,cz,sx,sy,sz]
// out (N,C,7,7,7) f32. dims_max=32, R=7. L=c1-c0 in [2,13] => bin widths in [1,3].
//
// Structure: grid = (proposal n, chunk of 256 outputs). 16 ch-groups x 343 bins
// = 5488 thread-outputs per proposal across 22 blocks (8 CTA/SM capable,
// fine-grained balance). Bounds once per block in smem.
// Inner w-window: first element loaded unconditionally (4 channels batched),
// +1/+2 elements PREDICATED on actual width -> wavefronts only for real bytes,
// but all loads of a (d,h) issue before any dependent FMAX (high MLP).

#define R_BINS 7
#define C_CH   64
#define DIMMAX 32
#define CG     4
#define NTHREADS 256
#define CHSTRIDE 32768              // floats per (b,c) volume: 32^3
#define PER_PROP (16 * 343)         // 5488
#define CHUNKS   ((PER_PROP + NTHREADS - 1) / NTHREADS)   // 22

__global__ __launch_bounds__(NTHREADS) void crop_roi_kernel(
        const float* __restrict__ f,
        const float* __restrict__ props,
        float* __restrict__ out) {
    const int n   = blockIdx.x;
    const int tid = threadIdx.x;

    __shared__ int sS[3][R_BINS], sE[3][R_BINS];
    __shared__ int sB;

    // ---- bounds (21 threads), bitwise-identical to reference math ----
    if (tid < 3 * R_BINS) {
        const int ax = tid / R_BINS;
        const int bi = tid - ax * R_BINS;
        const float* p = props + (size_t)n * 8;
        if (tid == 0) sB = (int)p[0];
        float center = __ldg(p + 2 + ax);
        float side   = __ldg(p + 5 + ax);
        // *0.5f and *0.25f exact (powers of two) -> matches jnp arithmetic
        int c0 = (int)floorf((center - 0.5f * side) * 0.25f);
        int c1 = (int)ceilf ((center + 0.5f * side) * 0.25f);
        c0 = max(c0, 0);
        c1 = min(c1, DIMMAX);
        int L  = c1 - c0;
        int ss = c0 + (bi * L) / R_BINS;                     // floor div
        int ee = c0 + ((bi + 1) * L + R_BINS - 1) / R_BINS;  // ceil div
        ee = min(ee, ss + 6);                                // K cap (safety)
        sS[ax][bi] = ss;
        sE[ax][bi] = ee;
    }
    __syncthreads();

    const int local = blockIdx.y * NTHREADS + tid;
    if (local >= PER_PROP) return;

    const int cg  = local / 343;
    const int bin = local - cg * 343;
    const int i   = bin / 49;
    const int rem = bin - i * 49;
    const int j   = rem / 7;
    const int k   = rem - j * 7;

    const int sd = sS[0][i], ed = sE[0][i];
    const int sh = sS[1][j], eh = sE[1][j];
    const int w0 = sS[2][k];
    const int ww = sE[2][k] - w0;           // width in [1,3]

    const float* base = f + (((size_t)sB * C_CH + cg * CG) << 15) + w0;

    const float NEG = -3.402823466e+38f;    // finfo(float32).min
    float m0 = NEG, m1 = NEG, m2 = NEG, m3 = NEG;

    for (int d = sd; d < ed; d++) {
        const float* pd = base + (d << 10);
        for (int h = sh; h < eh; h++) {
            const float* p = pd + (h << 5);
            // w = w0: unconditional, 4 channels at fixed immediate offsets
            float a0 = p[0 * CHSTRIDE];
            float a1 = p[1 * CHSTRIDE];
            float a2 = p[2 * CHSTRIDE];
            float a3 = p[3 * CHSTRIDE];
            if (ww > 1) {   // w = w0+1: predicated -> no traffic when width==1
                a0 = fmaxf(a0, p[1 + 0 * CHSTRIDE]);
                a1 = fmaxf(a1, p[1 + 1 * CHSTRIDE]);
                a2 = fmaxf(a2, p[1 + 2 * CHSTRIDE]);
                a3 = fmaxf(a3, p[1 + 3 * CHSTRIDE]);
            }
            if (ww > 2) {   // w = w0+2
                a0 = fmaxf(a0, p[2 + 0 * CHSTRIDE]);
                a1 = fmaxf(a1, p[2 + 1 * CHSTRIDE]);
                a2 = fmaxf(a2, p[2 + 2 * CHSTRIDE]);
                a3 = fmaxf(a3, p[2 + 3 * CHSTRIDE]);
            }
            m0 = fmaxf(m0, a0);
            m1 = fmaxf(m1, a1);
            m2 = fmaxf(m2, a2);
            m3 = fmaxf(m3, a3);
        }
    }

    size_t o = ((size_t)n * C_CH + cg * CG) * 343 + bin;
    out[o]           = m0;
    out[o + 1 * 343] = m1;
    out[o + 2 * 343] = m2;
    out[o + 3 * 343] = m3;
}

extern "C" void kernel_launch(void* const* d_in, const int* in_sizes, int n_in,
                              void* d_out, int out_size) {
    const float* f     = (const float*)d_in[0];
    const float* props = (const float*)d_in[2];
    float* out = (float*)d_out;

    int n_props = in_sizes[2] / 8;
    dim3 grid(n_props, CHUNKS);
    crop_roi_kernel<<<grid, NTHREADS>>>(f, props, out);
}